// round 1
// baseline (speedup 1.0000x reference)
#include <cuda_runtime.h>
#include <cstdint>
#include <cstddef>

#define NUc 100000
#define NTc 200000
#define Ec  1000000

// ---------------- scratch (device globals; no allocation) ----------------
__device__ __align__(128) float g_hu [NUc*64];
__device__ __align__(128) float g_ht [NTc*64];
__device__ __align__(128) float g_mu0[NUc*64];
__device__ __align__(128) float g_mu1[NUc*64];
__device__ __align__(128) float g_mt0[NTc*64];
__device__ __align__(128) float g_mt1[NTc*64];
__device__ __align__(128) float g_accu[NUc*64];
__device__ __align__(128) float g_acct[NTc*64];
__device__ float g_dinv_u2u[NUc];   // counts then dinv (in place)
__device__ float g_dinv_t2t[NTc];
__device__ float g_ds_u2t[NUc];
__device__ float g_dd_u2t[NTc];
__device__ float g_ds_t2u[NTc];
__device__ float g_dd_t2u[NUc];
__device__ float g_colsum[128];

// ---------------- helpers ----------------
__device__ __forceinline__ void red_add_v4(float* addr, float4 v) {
    asm volatile("red.global.add.v4.f32 [%0], {%1,%2,%3,%4};"
                 :: "l"(addr), "f"(v.x), "f"(v.y), "f"(v.z), "f"(v.w) : "memory");
}

// ---------------- degree / norm ----------------
__global__ void zero_deg_kernel() {
    int i = blockIdx.x * blockDim.x + threadIdx.x;
    if (i < NUc) { g_dinv_u2u[i] = 0.f; g_ds_u2t[i] = 0.f; g_dd_t2u[i] = 0.f; }
    if (i < NTc) { g_dinv_t2t[i] = 0.f; g_dd_u2t[i] = 0.f; g_ds_t2u[i] = 0.f; }
}

__global__ void count_all_kernel(const int* __restrict__ eu2u, const int* __restrict__ et2t,
                                 const int* __restrict__ eu2t, const int* __restrict__ et2u) {
    int e = blockIdx.x * blockDim.x + threadIdx.x;
    if (e >= Ec) return;
    atomicAdd(&g_dinv_u2u[eu2u[Ec + e]], 1.f);
    atomicAdd(&g_dinv_t2t[et2t[Ec + e]], 1.f);
    atomicAdd(&g_ds_u2t [eu2t[e]],      1.f);
    atomicAdd(&g_dd_u2t [eu2t[Ec + e]], 1.f);
    atomicAdd(&g_ds_t2u [et2u[e]],      1.f);
    atomicAdd(&g_dd_t2u [et2u[Ec + e]], 1.f);
}

__global__ void dinv_all_kernel() {
    int i = blockIdx.x * blockDim.x + threadIdx.x;
    if (i < NUc) {
        g_dinv_u2u[i] = rsqrtf(g_dinv_u2u[i] + 1.f);          // self-loop: deg>=1 always
        float v = g_ds_u2t[i]; g_ds_u2t[i] = (v > 0.f) ? rsqrtf(v) : 0.f;
        v = g_dd_t2u[i];       g_dd_t2u[i] = (v > 0.f) ? rsqrtf(v) : 0.f;
    }
    if (i < NTc) {
        g_dinv_t2t[i] = rsqrtf(g_dinv_t2t[i] + 1.f);
        float v = g_dd_u2t[i]; g_dd_u2t[i] = (v > 0.f) ? rsqrtf(v) : 0.f;
        v = g_ds_t2u[i];       g_ds_t2u[i] = (v > 0.f) ? rsqrtf(v) : 0.f;
    }
}

// ---------------- GEMMs ----------------
// out[N,64] = A[N,K] @ W[K,64] + b ; block = 256 threads, 32 rows/block.
template<int K>
__device__ __forceinline__ void gemm_bias_impl(const float* __restrict__ A,
                                               const float* __restrict__ W,
                                               const float* __restrict__ b,
                                               float* __restrict__ out, int N) {
    __shared__ float Ws[K * 64];
    __shared__ float As[32 * (K + 1)];
    int t = threadIdx.x;
    for (int i = t; i < K * 64; i += 256) Ws[i] = W[i];
    int row0 = blockIdx.x * 32;
    for (int i = t; i < 32 * K; i += 256) {
        int r = i / K, c = i - r * K; int gr = row0 + r;
        As[r * (K + 1) + c] = (gr < N) ? A[(size_t)gr * K + c] : 0.f;
    }
    __syncthreads();
    int r = t >> 3, cseg = (t & 7) << 3;
    float acc[8];
#pragma unroll
    for (int i = 0; i < 8; i++) acc[i] = b[cseg + i];
#pragma unroll
    for (int k = 0; k < K; k++) {
        float a = As[r * (K + 1) + k];
#pragma unroll
        for (int i = 0; i < 8; i++) acc[i] += a * Ws[(k << 6) + cseg + i];
    }
    int gr = row0 + r;
    if (gr < N) {
        float4* p = (float4*)(out + ((size_t)gr << 6) + cseg);
        p[0] = make_float4(acc[0], acc[1], acc[2], acc[3]);
        p[1] = make_float4(acc[4], acc[5], acc[6], acc[7]);
    }
}

__global__ void embed_user_kernel(const float* __restrict__ x, const float* __restrict__ W,
                                  const float* __restrict__ b) {
    gemm_bias_impl<32>(x, W, b, g_hu, NUc);
}
__global__ void embed_txn_kernel(const float* __restrict__ x, const float* __restrict__ W,
                                 const float* __restrict__ b) {
    gemm_bias_impl<64>(x, W, b, g_ht, NTc);
}

// Dual-output transform: M0 = A@W0, M1 = A@W1 (no bias; biases added in finalize).
__device__ __forceinline__ void transform_dual_impl(const float* __restrict__ A,
                                                    const float* __restrict__ W0,
                                                    const float* __restrict__ W1,
                                                    float* __restrict__ M0,
                                                    float* __restrict__ M1, int N) {
    __shared__ float Ws0[64 * 64];
    __shared__ float Ws1[64 * 64];
    __shared__ float As[32 * 65];
    int t = threadIdx.x;
    for (int i = t; i < 4096; i += 256) { Ws0[i] = W0[i]; Ws1[i] = W1[i]; }
    int row0 = blockIdx.x * 32;
    for (int i = t; i < 32 * 64; i += 256) {
        int r = i >> 6, c = i & 63; int gr = row0 + r;
        As[r * 65 + c] = (gr < N) ? A[((size_t)gr << 6) + c] : 0.f;
    }
    __syncthreads();
    int r = t >> 3, cseg = (t & 7) << 3;
    float a0[8], a1[8];
#pragma unroll
    for (int i = 0; i < 8; i++) { a0[i] = 0.f; a1[i] = 0.f; }
#pragma unroll
    for (int k = 0; k < 64; k++) {
        float a = As[r * 65 + k];
#pragma unroll
        for (int i = 0; i < 8; i++) {
            a0[i] += a * Ws0[(k << 6) + cseg + i];
            a1[i] += a * Ws1[(k << 6) + cseg + i];
        }
    }
    int gr = row0 + r;
    if (gr < N) {
        float4* p0 = (float4*)(M0 + ((size_t)gr << 6) + cseg);
        p0[0] = make_float4(a0[0], a0[1], a0[2], a0[3]);
        p0[1] = make_float4(a0[4], a0[5], a0[6], a0[7]);
        float4* p1 = (float4*)(M1 + ((size_t)gr << 6) + cseg);
        p1[0] = make_float4(a1[0], a1[1], a1[2], a1[3]);
        p1[1] = make_float4(a1[4], a1[5], a1[6], a1[7]);
    }
}

__global__ void transform_u_kernel(const float* __restrict__ W0, const float* __restrict__ W1) {
    transform_dual_impl(g_hu, W0, W1, g_mu0, g_mu1, NUc);
}
__global__ void transform_t_kernel(const float* __restrict__ W0, const float* __restrict__ W1) {
    transform_dual_impl(g_ht, W0, W1, g_mt0, g_mt1, NTc);
}

// ---------------- self-loop init (writes acc, no zero-fill needed) ----------------
__global__ void selfinit_u_kernel() {
    int i = blockIdx.x * blockDim.x + threadIdx.x;
    if (i < NUc * 64) { float dv = g_dinv_u2u[i >> 6]; g_accu[i] = g_mu0[i] * dv * dv; }
}
__global__ void selfinit_t_kernel() {
    int i = blockIdx.x * blockDim.x + threadIdx.x;
    if (i < NTc * 64) { float dv = g_dinv_t2t[i >> 6]; g_acct[i] = g_mt0[i] * dv * dv; }
}

// ---------------- edge scatter: 16 threads / edge, vector RED ----------------
__device__ __forceinline__ void scatter_impl(const int* __restrict__ ei,
                                             const float* __restrict__ dinv_s,
                                             const float* __restrict__ dinv_d,
                                             const float* __restrict__ m,
                                             float* __restrict__ acc) {
    int tid = blockIdx.x * blockDim.x + threadIdx.x;
    int e = tid >> 4, q = tid & 15;
    if (e >= Ec) return;
    int s = __ldg(&ei[e]);
    int d = __ldg(&ei[Ec + e]);
    float norm = __ldg(&dinv_s[s]) * __ldg(&dinv_d[d]);
    float4 v = *(const float4*)(m + ((size_t)s << 6) + (q << 2));
    v.x *= norm; v.y *= norm; v.z *= norm; v.w *= norm;
    red_add_v4(acc + ((size_t)d << 6) + (q << 2), v);
}

__global__ void scatter_u2u_kernel(const int* __restrict__ ei) {
    scatter_impl(ei, g_dinv_u2u, g_dinv_u2u, g_mu0, g_accu);
}
__global__ void scatter_t2u_kernel(const int* __restrict__ ei) {
    scatter_impl(ei, g_ds_t2u, g_dd_t2u, g_mt1, g_accu);
}
__global__ void scatter_t2t_kernel(const int* __restrict__ ei) {
    scatter_impl(ei, g_dinv_t2t, g_dinv_t2t, g_mt0, g_acct);
}
__global__ void scatter_u2t_kernel(const int* __restrict__ ei) {
    scatter_impl(ei, g_ds_u2t, g_dd_u2t, g_mu1, g_acct);
}

// ---------------- finalize: h = relu(0.5*(acc + b_a + b_b)) ----------------
__global__ void finalize_u_kernel(const float* __restrict__ ba, const float* __restrict__ bb) {
    int i = blockIdx.x * blockDim.x + threadIdx.x;
    if (i < NUc * 64) { int c = i & 63; g_hu[i] = fmaxf(0.5f * (g_accu[i] + ba[c] + bb[c]), 0.f); }
}
__global__ void finalize_t_kernel(const float* __restrict__ ba, const float* __restrict__ bb) {
    int i = blockIdx.x * blockDim.x + threadIdx.x;
    if (i < NTc * 64) { int c = i & 63; g_ht[i] = fmaxf(0.5f * (g_acct[i] + ba[c] + bb[c]), 0.f); }
}

// ---------------- readout ----------------
__global__ void zero_colsum_kernel() {
    if (threadIdx.x < 128) g_colsum[threadIdx.x] = 0.f;
}
#define CS_BLOCKS 296
__global__ void colsum_u_kernel() {
    int t = blockIdx.x * blockDim.x + threadIdx.x;
    float s = 0.f;
    const int n = NUc * 64;
    for (int i = t; i < n; i += CS_BLOCKS * 256) s += g_hu[i];   // stride % 64 == 0 -> col fixed
    atomicAdd(&g_colsum[t & 63], s);
}
__global__ void colsum_t_kernel() {
    int t = blockIdx.x * blockDim.x + threadIdx.x;
    float s = 0.f;
    const int n = NTc * 64;
    for (int i = t; i < n; i += CS_BLOCKS * 256) s += g_ht[i];
    atomicAdd(&g_colsum[64 + (t & 63)], s);
}

__global__ void mlp_kernel(const float* __restrict__ W1, const float* __restrict__ b1,
                           const float* __restrict__ W2, const float* __restrict__ b2,
                           float* __restrict__ out) {
    __shared__ float x[64];
    __shared__ float y[64];
    int t = threadIdx.x;
    x[t] = 0.5f * (g_colsum[t] * (1.f / NUc) + g_colsum[64 + t] * (1.f / NTc));
    __syncthreads();
    float s = b1[t];
    for (int k = 0; k < 64; k++) s += x[k] * W1[k * 64 + t];
    y[t] = fmaxf(s, 0.f) * W2[t];
    __syncthreads();
    if (t == 0) {
        float o = b2[0];
        for (int j = 0; j < 64; j++) o += y[j];
        out[0] = 1.f / (1.f + expf(-o));
    }
}

// ---------------- launch ----------------
extern "C" void kernel_launch(void* const* d_in, const int* in_sizes, int n_in,
                              void* d_out, int out_size) {
    const float* x_user     = (const float*)d_in[0];
    const float* x_txn      = (const float*)d_in[1];
    const int*   ei_u2u     = (const int*)d_in[2];
    const int*   ei_t2t     = (const int*)d_in[3];
    const int*   ei_u2t     = (const int*)d_in[4];
    const int*   ei_t2u     = (const int*)d_in[5];
    const float* W_emb_user = (const float*)d_in[6];
    const float* b_emb_user = (const float*)d_in[7];
    const float* W_emb_txn  = (const float*)d_in[8];
    const float* b_emb_txn  = (const float*)d_in[9];
    const float* conv_W     = (const float*)d_in[10];
    const float* conv_b     = (const float*)d_in[11];
    const float* W1         = (const float*)d_in[12];
    const float* b1         = (const float*)d_in[13];
    const float* W2         = (const float*)d_in[14];
    const float* b2         = (const float*)d_in[15];
    float* out = (float*)d_out;

    // degrees / norms (edge structure is layer-invariant)
    zero_deg_kernel<<<(NTc + 255) / 256, 256>>>();
    count_all_kernel<<<(Ec + 255) / 256, 256>>>(ei_u2u, ei_t2t, ei_u2t, ei_t2u);
    dinv_all_kernel<<<(NTc + 255) / 256, 256>>>();

    // embeddings
    embed_user_kernel<<<(NUc + 31) / 32, 256>>>(x_user, W_emb_user, b_emb_user);
    embed_txn_kernel<<<(NTc + 31) / 32, 256>>>(x_txn, W_emb_txn, b_emb_txn);

    const int SC_BLOCKS = (Ec * 16 + 255) / 256;   // 62500
    for (int l = 0; l < 3; l++) {
        const float* W = conv_W + (size_t)l * 4 * 64 * 64;
        const float* B = conv_b + (size_t)l * 4 * 64;
        transform_u_kernel<<<(NUc + 31) / 32, 256>>>(W + 0 * 4096, W + 2 * 4096);
        transform_t_kernel<<<(NTc + 31) / 32, 256>>>(W + 1 * 4096, W + 3 * 4096);
        selfinit_u_kernel<<<(NUc * 64 + 255) / 256, 256>>>();
        selfinit_t_kernel<<<(NTc * 64 + 255) / 256, 256>>>();
        scatter_u2u_kernel<<<SC_BLOCKS, 256>>>(ei_u2u);
        scatter_t2u_kernel<<<SC_BLOCKS, 256>>>(ei_t2u);
        scatter_t2t_kernel<<<SC_BLOCKS, 256>>>(ei_t2t);
        scatter_u2t_kernel<<<SC_BLOCKS, 256>>>(ei_u2t);
        finalize_u_kernel<<<(NUc * 64 + 255) / 256, 256>>>(B + 0 * 64, B + 3 * 64);
        finalize_t_kernel<<<(NTc * 64 + 255) / 256, 256>>>(B + 1 * 64, B + 2 * 64);
    }

    zero_colsum_kernel<<<1, 128>>>();
    colsum_u_kernel<<<CS_BLOCKS, 256>>>();
    colsum_t_kernel<<<CS_BLOCKS, 256>>>();
    mlp_kernel<<<1, 64>>>(W1, b1, W2, b2, out);
}

// round 2
// speedup vs baseline: 1.8714x; 1.8714x over previous
#include <cuda_runtime.h>
#include <cstdint>
#include <cstddef>

#define NUc 100000
#define NTc 200000
#define Ec  1000000

typedef unsigned long long u64;

// ---------------- scratch (device globals; no allocation) ----------------
__device__ __align__(128) float g_hu [NUc*64];
__device__ __align__(128) float g_ht [NTc*64];
__device__ __align__(128) float g_mu0[NUc*64];   // (hu@W_u2u) * d_u2u[row]
__device__ __align__(128) float g_mu1[NUc*64];   // (hu@W_u2t) * ds_u2t[row]
__device__ __align__(128) float g_mt0[NTc*64];   // (ht@W_t2t) * d_t2t[row]
__device__ __align__(128) float g_mt1[NTc*64];   // (ht@W_t2u) * ds_t2u[row]

__device__ int g_c_u2u[NUc];
__device__ int g_c_t2t[NTc];
__device__ int g_c_u2t_d[NTc];
__device__ int g_c_t2u_d[NUc];
__device__ int g_c_u2t_s[NUc];
__device__ int g_c_t2u_s[NTc];

__device__ float g_d_u2u[NUc];    // rsqrt(deg+1) (incl self loop)
__device__ float g_d_t2t[NTc];
__device__ float g_ds_u2t[NUc];
__device__ float g_dd_u2t[NTc];
__device__ float g_ds_t2u[NTc];
__device__ float g_dd_t2u[NUc];

__device__ int g_off_u2u[NUc+1];
__device__ int g_off_t2t[NTc+1];
__device__ int g_off_u2t[NTc+1];
__device__ int g_off_t2u[NUc+1];
__device__ int g_cur_u2u[NUc];
__device__ int g_cur_t2t[NTc];
__device__ int g_cur_u2t[NTc];
__device__ int g_cur_t2u[NUc];
__device__ int g_csr_u2u[Ec];
__device__ int g_csr_t2t[Ec];
__device__ int g_csr_u2t[Ec];
__device__ int g_csr_t2u[Ec];

__device__ float g_colsum[128];

// ---------------- f32x2 helpers ----------------
__device__ __forceinline__ u64 pack2(float a) {
    u64 r; asm("mov.b64 %0,{%1,%1};" : "=l"(r) : "f"(a)); return r;
}
__device__ __forceinline__ u64 pack2ab(float a, float b) {
    u64 r; asm("mov.b64 %0,{%1,%2};" : "=l"(r) : "f"(a), "f"(b)); return r;
}
__device__ __forceinline__ void fma2(u64& acc, u64 a, u64 w) {
    asm("fma.rn.f32x2 %0,%1,%2,%3;" : "=l"(acc) : "l"(a), "l"(w), "l"(acc));
}
__device__ __forceinline__ float2 unpack2(u64 v) {
    float2 f; asm("mov.b64 {%0,%1},%2;" : "=f"(f.x), "=f"(f.y) : "l"(v)); return f;
}

// ---------------- setup: counts ----------------
__global__ void zero_cnt_kernel() {
    int i = blockIdx.x * blockDim.x + threadIdx.x;
    if (i < NUc) { g_c_u2u[i] = 0; g_c_u2t_s[i] = 0; g_c_t2u_d[i] = 0; }
    if (i < NTc) { g_c_t2t[i] = 0; g_c_u2t_d[i] = 0; g_c_t2u_s[i] = 0; }
    if (i < 128) g_colsum[i] = 0.f;
}

__global__ void count_kernel(const int* __restrict__ eu2u, const int* __restrict__ et2t,
                             const int* __restrict__ eu2t, const int* __restrict__ et2u) {
    int e = blockIdx.x * blockDim.x + threadIdx.x;
    if (e >= Ec) return;
    atomicAdd(&g_c_u2u[eu2u[Ec + e]], 1);
    atomicAdd(&g_c_t2t[et2t[Ec + e]], 1);
    atomicAdd(&g_c_u2t_d[eu2t[Ec + e]], 1);
    atomicAdd(&g_c_u2t_s[eu2t[e]],      1);
    atomicAdd(&g_c_t2u_d[et2u[Ec + e]], 1);
    atomicAdd(&g_c_t2u_s[et2u[e]],      1);
}

// ---------------- setup: 4 exclusive scans (one block each) ----------------
__global__ void scan4_kernel() {
    const int* cnt; int* off; int* cur; int n;
    switch (blockIdx.x) {
        case 0:  cnt = g_c_u2u;   off = g_off_u2u; cur = g_cur_u2u; n = NUc; break;
        case 1:  cnt = g_c_t2t;   off = g_off_t2t; cur = g_cur_t2t; n = NTc; break;
        case 2:  cnt = g_c_u2t_d; off = g_off_u2t; cur = g_cur_u2t; n = NTc; break;
        default: cnt = g_c_t2u_d; off = g_off_t2u; cur = g_cur_t2u; n = NUc; break;
    }
    __shared__ int sh[1024];
    int tid = threadIdx.x;
    int chunk = (n + 1023) >> 10;
    int start = tid * chunk;
    int end = min(start + chunk, n);
    int s = 0;
    for (int i = start; i < end; i++) s += cnt[i];
    sh[tid] = s;
    __syncthreads();
    for (int d = 1; d < 1024; d <<= 1) {
        int v = (tid >= d) ? sh[tid - d] : 0;
        __syncthreads();
        sh[tid] += v;
        __syncthreads();
    }
    int run = sh[tid] - s;   // exclusive prefix of this chunk
    for (int i = start; i < end; i++) { off[i] = run; cur[i] = run; run += cnt[i]; }
    if (start < n && end == n) off[n] = run;
}

// ---------------- setup: CSR fill ----------------
__global__ void fill_kernel(const int* __restrict__ eu2u, const int* __restrict__ et2t,
                            const int* __restrict__ eu2t, const int* __restrict__ et2u) {
    int e = blockIdx.x * blockDim.x + threadIdx.x;
    if (e >= Ec) return;
    int p;
    p = atomicAdd(&g_cur_u2u[eu2u[Ec + e]], 1); g_csr_u2u[p] = eu2u[e];
    p = atomicAdd(&g_cur_t2t[et2t[Ec + e]], 1); g_csr_t2t[p] = et2t[e];
    p = atomicAdd(&g_cur_u2t[eu2t[Ec + e]], 1); g_csr_u2t[p] = eu2t[e];
    p = atomicAdd(&g_cur_t2u[et2u[Ec + e]], 1); g_csr_t2u[p] = et2u[e];
}

__global__ void dinv_kernel() {
    int i = blockIdx.x * blockDim.x + threadIdx.x;
    if (i < NUc) {
        g_d_u2u[i] = rsqrtf((float)g_c_u2u[i] + 1.f);
        int cs = g_c_u2t_s[i]; g_ds_u2t[i] = (cs > 0) ? rsqrtf((float)cs) : 0.f;
        int cd = g_c_t2u_d[i]; g_dd_t2u[i] = (cd > 0) ? rsqrtf((float)cd) : 0.f;
    }
    if (i < NTc) {
        g_d_t2t[i] = rsqrtf((float)g_c_t2t[i] + 1.f);
        int cd = g_c_u2t_d[i]; g_dd_u2t[i] = (cd > 0) ? rsqrtf((float)cd) : 0.f;
        int cs = g_c_t2u_s[i]; g_ds_t2u[i] = (cs > 0) ? rsqrtf((float)cs) : 0.f;
    }
}

// ---------------- GEMMs: 128 rows/block, 4 rows/thread, f32x2 FMA ----------------
// embed: O[N,64] = A[N,K] @ W[K,64] + b
template<int K>
__device__ __forceinline__ void embed_impl(const float* __restrict__ A,
                                           const float* __restrict__ W,
                                           const float* __restrict__ b,
                                           float* __restrict__ O, int N) {
    extern __shared__ float sm[];
    float* Ws = sm;                 // K*64
    float* As = sm + K * 64;        // 128*(K+1)
    constexpr int KS = K + 1;
    int t = threadIdx.x;
    for (int i = t; i < K * 64; i += 256) Ws[i] = W[i];
    int row0 = blockIdx.x * 128;
    for (int i = t; i < 128 * K; i += 256) {
        int r = i / K, c = i & (K - 1);
        int gr = row0 + r;
        As[r * KS + c] = (gr < N) ? A[(size_t)gr * K + c] : 0.f;
    }
    __syncthreads();
    int cg = t & 7, r0 = (t >> 3) << 2;
    u64 binit[4];
#pragma unroll
    for (int j = 0; j < 4; j++)
        binit[j] = pack2ab(b[(cg << 3) + (j << 1)], b[(cg << 3) + (j << 1) + 1]);
    u64 acc[4][4];
#pragma unroll
    for (int rr = 0; rr < 4; rr++)
#pragma unroll
        for (int j = 0; j < 4; j++) acc[rr][j] = binit[j];
#pragma unroll 4
    for (int k = 0; k < K; k++) {
        const float* wp = &Ws[(k << 6) + (cg << 3)];
        ulonglong2 wa = *(const ulonglong2*)wp;
        ulonglong2 wb = *(const ulonglong2*)(wp + 4);
#pragma unroll
        for (int rr = 0; rr < 4; rr++) {
            u64 a2 = pack2(As[(r0 + rr) * KS + k]);
            fma2(acc[rr][0], a2, wa.x);
            fma2(acc[rr][1], a2, wa.y);
            fma2(acc[rr][2], a2, wb.x);
            fma2(acc[rr][3], a2, wb.y);
        }
    }
#pragma unroll
    for (int rr = 0; rr < 4; rr++) {
        int gr = row0 + r0 + rr;
        if (gr < N) {
            float2 p0 = unpack2(acc[rr][0]), p1 = unpack2(acc[rr][1]);
            float2 p2 = unpack2(acc[rr][2]), p3 = unpack2(acc[rr][3]);
            float4* o = (float4*)(O + ((size_t)gr << 6) + (cg << 3));
            o[0] = make_float4(p0.x, p0.y, p1.x, p1.y);
            o[1] = make_float4(p2.x, p2.y, p3.x, p3.y);
        }
    }
}

// dual transform: O0 = (A@W0)*sc0[row], O1 = (A@W1)*sc1[row]  (K = 64)
__device__ __forceinline__ void dual_impl(const float* __restrict__ A,
                                          const float* __restrict__ W0,
                                          const float* __restrict__ W1,
                                          const float* __restrict__ sc0,
                                          const float* __restrict__ sc1,
                                          float* __restrict__ O0,
                                          float* __restrict__ O1, int N) {
    extern __shared__ float sm[];
    float* Ws0 = sm;                  // 4096
    float* Ws1 = sm + 4096;           // 4096
    float* As  = sm + 8192;           // 128*65
    int t = threadIdx.x;
    for (int i = t; i < 4096; i += 256) { Ws0[i] = W0[i]; Ws1[i] = W1[i]; }
    int row0 = blockIdx.x * 128;
    for (int i = t; i < 128 * 64; i += 256) {
        int r = i >> 6, c = i & 63;
        int gr = row0 + r;
        As[r * 65 + c] = (gr < N) ? A[((size_t)gr << 6) + c] : 0.f;
    }
    __syncthreads();
    int cg = t & 7, r0 = (t >> 3) << 2;
    u64 acc0[4][4], acc1[4][4];
#pragma unroll
    for (int rr = 0; rr < 4; rr++)
#pragma unroll
        for (int j = 0; j < 4; j++) { acc0[rr][j] = 0ull; acc1[rr][j] = 0ull; }
#pragma unroll 4
    for (int k = 0; k < 64; k++) {
        const float* wp0 = &Ws0[(k << 6) + (cg << 3)];
        const float* wp1 = &Ws1[(k << 6) + (cg << 3)];
        ulonglong2 w0a = *(const ulonglong2*)wp0;
        ulonglong2 w0b = *(const ulonglong2*)(wp0 + 4);
        ulonglong2 w1a = *(const ulonglong2*)wp1;
        ulonglong2 w1b = *(const ulonglong2*)(wp1 + 4);
#pragma unroll
        for (int rr = 0; rr < 4; rr++) {
            u64 a2 = pack2(As[(r0 + rr) * 65 + k]);
            fma2(acc0[rr][0], a2, w0a.x);
            fma2(acc0[rr][1], a2, w0a.y);
            fma2(acc0[rr][2], a2, w0b.x);
            fma2(acc0[rr][3], a2, w0b.y);
            fma2(acc1[rr][0], a2, w1a.x);
            fma2(acc1[rr][1], a2, w1a.y);
            fma2(acc1[rr][2], a2, w1b.x);
            fma2(acc1[rr][3], a2, w1b.y);
        }
    }
#pragma unroll
    for (int rr = 0; rr < 4; rr++) {
        int gr = row0 + r0 + rr;
        if (gr < N) {
            float s0 = sc0[gr], s1 = sc1[gr];
            float2 p0 = unpack2(acc0[rr][0]), p1 = unpack2(acc0[rr][1]);
            float2 p2 = unpack2(acc0[rr][2]), p3 = unpack2(acc0[rr][3]);
            float4* o0 = (float4*)(O0 + ((size_t)gr << 6) + (cg << 3));
            o0[0] = make_float4(p0.x * s0, p0.y * s0, p1.x * s0, p1.y * s0);
            o0[1] = make_float4(p2.x * s0, p2.y * s0, p3.x * s0, p3.y * s0);
            p0 = unpack2(acc1[rr][0]); p1 = unpack2(acc1[rr][1]);
            p2 = unpack2(acc1[rr][2]); p3 = unpack2(acc1[rr][3]);
            float4* o1 = (float4*)(O1 + ((size_t)gr << 6) + (cg << 3));
            o1[0] = make_float4(p0.x * s1, p0.y * s1, p1.x * s1, p1.y * s1);
            o1[1] = make_float4(p2.x * s1, p2.y * s1, p3.x * s1, p3.y * s1);
        }
    }
}

__global__ void __launch_bounds__(256) embed_user_kernel(const float* __restrict__ x,
                                                         const float* __restrict__ W,
                                                         const float* __restrict__ b) {
    embed_impl<32>(x, W, b, g_hu, NUc);
}
__global__ void __launch_bounds__(256) embed_txn_kernel(const float* __restrict__ x,
                                                        const float* __restrict__ W,
                                                        const float* __restrict__ b) {
    embed_impl<64>(x, W, b, g_ht, NTc);
}
__global__ void __launch_bounds__(256) transform_u_kernel(const float* __restrict__ W0,
                                                          const float* __restrict__ W1) {
    dual_impl(g_hu, W0, W1, g_d_u2u, g_ds_u2t, g_mu0, g_mu1, NUc);
}
__global__ void __launch_bounds__(256) transform_t_kernel(const float* __restrict__ W0,
                                                          const float* __restrict__ W1) {
    dual_impl(g_ht, W0, W1, g_d_t2t, g_ds_t2u, g_mt0, g_mt1, NTc);
}

// ---------------- fused gather-aggregate + bias + relu (no atomics) ----------------
// 8 threads per dst node, each owns 8 columns (2 float4).
__global__ void __launch_bounds__(256) agg_u_kernel(const float* __restrict__ bA,
                                                    const float* __restrict__ bB) {
    int idx = blockIdx.x * 256 + threadIdx.x;
    int g = idx >> 3;
    if (g >= NUc) return;
    int c0 = (idx & 7) << 3;
    // u2u (incl self loop): acc = mu0[self] + sum mu0[src]; × d_u2u[g]
    const float4* sp = (const float4*)(g_mu0 + ((size_t)g << 6) + c0);
    float4 a0 = __ldg(sp), a1 = __ldg(sp + 1);
    int e = g_off_u2u[g], end = g_off_u2u[g + 1];
    for (; e < end; e++) {
        int s = g_csr_u2u[e];
        const float4* p = (const float4*)(g_mu0 + ((size_t)s << 6) + c0);
        float4 v0 = __ldg(p), v1 = __ldg(p + 1);
        a0.x += v0.x; a0.y += v0.y; a0.z += v0.z; a0.w += v0.w;
        a1.x += v1.x; a1.y += v1.y; a1.z += v1.z; a1.w += v1.w;
    }
    float du = g_d_u2u[g];
    // t2u: × dd_t2u[g]
    float4 b0 = make_float4(0.f, 0.f, 0.f, 0.f), b1 = b0;
    e = g_off_t2u[g]; end = g_off_t2u[g + 1];
    for (; e < end; e++) {
        int s = g_csr_t2u[e];
        const float4* p = (const float4*)(g_mt1 + ((size_t)s << 6) + c0);
        float4 v0 = __ldg(p), v1 = __ldg(p + 1);
        b0.x += v0.x; b0.y += v0.y; b0.z += v0.z; b0.w += v0.w;
        b1.x += v1.x; b1.y += v1.y; b1.z += v1.z; b1.w += v1.w;
    }
    float dt = g_dd_t2u[g];
    float4 bAv0 = __ldg((const float4*)(bA + c0)), bAv1 = __ldg((const float4*)(bA + c0 + 4));
    float4 bBv0 = __ldg((const float4*)(bB + c0)), bBv1 = __ldg((const float4*)(bB + c0 + 4));
    float4 o0, o1;
    o0.x = fmaxf(0.5f * (du * a0.x + dt * b0.x + bAv0.x + bBv0.x), 0.f);
    o0.y = fmaxf(0.5f * (du * a0.y + dt * b0.y + bAv0.y + bBv0.y), 0.f);
    o0.z = fmaxf(0.5f * (du * a0.z + dt * b0.z + bAv0.z + bBv0.z), 0.f);
    o0.w = fmaxf(0.5f * (du * a0.w + dt * b0.w + bAv0.w + bBv0.w), 0.f);
    o1.x = fmaxf(0.5f * (du * a1.x + dt * b1.x + bAv1.x + bBv1.x), 0.f);
    o1.y = fmaxf(0.5f * (du * a1.y + dt * b1.y + bAv1.y + bBv1.y), 0.f);
    o1.z = fmaxf(0.5f * (du * a1.z + dt * b1.z + bAv1.z + bBv1.z), 0.f);
    o1.w = fmaxf(0.5f * (du * a1.w + dt * b1.w + bAv1.w + bBv1.w), 0.f);
    float4* op = (float4*)(g_hu + ((size_t)g << 6) + c0);
    op[0] = o0; op[1] = o1;
}

__global__ void __launch_bounds__(256) agg_t_kernel(const float* __restrict__ bA,
                                                    const float* __restrict__ bB) {
    int idx = blockIdx.x * 256 + threadIdx.x;
    int g = idx >> 3;
    if (g >= NTc) return;
    int c0 = (idx & 7) << 3;
    const float4* sp = (const float4*)(g_mt0 + ((size_t)g << 6) + c0);
    float4 a0 = __ldg(sp), a1 = __ldg(sp + 1);
    int e = g_off_t2t[g], end = g_off_t2t[g + 1];
    for (; e < end; e++) {
        int s = g_csr_t2t[e];
        const float4* p = (const float4*)(g_mt0 + ((size_t)s << 6) + c0);
        float4 v0 = __ldg(p), v1 = __ldg(p + 1);
        a0.x += v0.x; a0.y += v0.y; a0.z += v0.z; a0.w += v0.w;
        a1.x += v1.x; a1.y += v1.y; a1.z += v1.z; a1.w += v1.w;
    }
    float du = g_d_t2t[g];
    float4 b0 = make_float4(0.f, 0.f, 0.f, 0.f), b1 = b0;
    e = g_off_u2t[g]; end = g_off_u2t[g + 1];
    for (; e < end; e++) {
        int s = g_csr_u2t[e];
        const float4* p = (const float4*)(g_mu1 + ((size_t)s << 6) + c0);
        float4 v0 = __ldg(p), v1 = __ldg(p + 1);
        b0.x += v0.x; b0.y += v0.y; b0.z += v0.z; b0.w += v0.w;
        b1.x += v1.x; b1.y += v1.y; b1.z += v1.z; b1.w += v1.w;
    }
    float dt = g_dd_u2t[g];
    float4 bAv0 = __ldg((const float4*)(bA + c0)), bAv1 = __ldg((const float4*)(bA + c0 + 4));
    float4 bBv0 = __ldg((const float4*)(bB + c0)), bBv1 = __ldg((const float4*)(bB + c0 + 4));
    float4 o0, o1;
    o0.x = fmaxf(0.5f * (du * a0.x + dt * b0.x + bAv0.x + bBv0.x), 0.f);
    o0.y = fmaxf(0.5f * (du * a0.y + dt * b0.y + bAv0.y + bBv0.y), 0.f);
    o0.z = fmaxf(0.5f * (du * a0.z + dt * b0.z + bAv0.z + bBv0.z), 0.f);
    o0.w = fmaxf(0.5f * (du * a0.w + dt * b0.w + bAv0.w + bBv0.w), 0.f);
    o1.x = fmaxf(0.5f * (du * a1.x + dt * b1.x + bAv1.x + bBv1.x), 0.f);
    o1.y = fmaxf(0.5f * (du * a1.y + dt * b1.y + bAv1.y + bBv1.y), 0.f);
    o1.z = fmaxf(0.5f * (du * a1.z + dt * b1.z + bAv1.z + bBv1.z), 0.f);
    o1.w = fmaxf(0.5f * (du * a1.w + dt * b1.w + bAv1.w + bBv1.w), 0.f);
    float4* op = (float4*)(g_ht + ((size_t)g << 6) + c0);
    op[0] = o0; op[1] = o1;
}

// ---------------- readout ----------------
#define CS_BLOCKS 296
__global__ void colsum_u_kernel() {
    int t = blockIdx.x * blockDim.x + threadIdx.x;
    float s = 0.f;
    const int n = NUc * 64;
    for (int i = t; i < n; i += CS_BLOCKS * 256) s += g_hu[i];
    atomicAdd(&g_colsum[t & 63], s);
}
__global__ void colsum_t_kernel() {
    int t = blockIdx.x * blockDim.x + threadIdx.x;
    float s = 0.f;
    const int n = NTc * 64;
    for (int i = t; i < n; i += CS_BLOCKS * 256) s += g_ht[i];
    atomicAdd(&g_colsum[64 + (t & 63)], s);
}

__global__ void mlp_kernel(const float* __restrict__ W1, const float* __restrict__ b1,
                           const float* __restrict__ W2, const float* __restrict__ b2,
                           float* __restrict__ out) {
    __shared__ float x[64];
    __shared__ float y[64];
    int t = threadIdx.x;
    x[t] = 0.5f * (g_colsum[t] * (1.f / NUc) + g_colsum[64 + t] * (1.f / NTc));
    __syncthreads();
    float s = b1[t];
    for (int k = 0; k < 64; k++) s += x[k] * W1[k * 64 + t];
    y[t] = fmaxf(s, 0.f) * W2[t];
    __syncthreads();
    if (t == 0) {
        float o = b2[0];
        for (int j = 0; j < 64; j++) o += y[j];
        out[0] = 1.f / (1.f + expf(-o));
    }
}

// ---------------- launch ----------------
extern "C" void kernel_launch(void* const* d_in, const int* in_sizes, int n_in,
                              void* d_out, int out_size) {
    const float* x_user     = (const float*)d_in[0];
    const float* x_txn      = (const float*)d_in[1];
    const int*   ei_u2u     = (const int*)d_in[2];
    const int*   ei_t2t     = (const int*)d_in[3];
    const int*   ei_u2t     = (const int*)d_in[4];
    const int*   ei_t2u     = (const int*)d_in[5];
    const float* W_emb_user = (const float*)d_in[6];
    const float* b_emb_user = (const float*)d_in[7];
    const float* W_emb_txn  = (const float*)d_in[8];
    const float* b_emb_txn  = (const float*)d_in[9];
    const float* conv_W     = (const float*)d_in[10];
    const float* conv_b     = (const float*)d_in[11];
    const float* W1         = (const float*)d_in[12];
    const float* b1         = (const float*)d_in[13];
    const float* W2         = (const float*)d_in[14];
    const float* b2         = (const float*)d_in[15];
    float* out = (float*)d_out;

    const int SMEM_E32  = (32 * 64 + 128 * 33) * 4;          // 25088
    const int SMEM_E64  = (64 * 64 + 128 * 65) * 4;          // 49664
    const int SMEM_DUAL = (2 * 64 * 64 + 128 * 65) * 4;      // 66048
    cudaFuncSetAttribute(embed_txn_kernel, cudaFuncAttributeMaxDynamicSharedMemorySize, SMEM_E64);
    cudaFuncSetAttribute(transform_u_kernel, cudaFuncAttributeMaxDynamicSharedMemorySize, SMEM_DUAL);
    cudaFuncSetAttribute(transform_t_kernel, cudaFuncAttributeMaxDynamicSharedMemorySize, SMEM_DUAL);

    // ---- CSR + norms (edge structure is layer-invariant) ----
    zero_cnt_kernel<<<(NTc + 255) / 256, 256>>>();
    count_kernel<<<(Ec + 255) / 256, 256>>>(ei_u2u, ei_t2t, ei_u2t, ei_t2u);
    scan4_kernel<<<4, 1024>>>();
    fill_kernel<<<(Ec + 255) / 256, 256>>>(ei_u2u, ei_t2t, ei_u2t, ei_t2u);
    dinv_kernel<<<(NTc + 255) / 256, 256>>>();

    // ---- embeddings ----
    embed_user_kernel<<<(NUc + 127) / 128, 256, SMEM_E32>>>(x_user, W_emb_user, b_emb_user);
    embed_txn_kernel<<<(NTc + 127) / 128, 256, SMEM_E64>>>(x_txn, W_emb_txn, b_emb_txn);

    // ---- layers ----
    for (int l = 0; l < 3; l++) {
        const float* W = conv_W + (size_t)l * 4 * 64 * 64;
        const float* B = conv_b + (size_t)l * 4 * 64;
        transform_u_kernel<<<(NUc + 127) / 128, 256, SMEM_DUAL>>>(W + 0 * 4096, W + 2 * 4096);
        transform_t_kernel<<<(NTc + 127) / 128, 256, SMEM_DUAL>>>(W + 1 * 4096, W + 3 * 4096);
        agg_u_kernel<<<(NUc * 8 + 255) / 256, 256>>>(B + 0 * 64, B + 3 * 64);
        agg_t_kernel<<<(NTc * 8 + 255) / 256, 256>>>(B + 1 * 64, B + 2 * 64);
    }

    // ---- readout ----
    colsum_u_kernel<<<CS_BLOCKS, 256>>>();
    colsum_t_kernel<<<CS_BLOCKS, 256>>>();
    mlp_kernel<<<1, 64>>>(W1, b1, W2, b2, out);
}

// round 3
// speedup vs baseline: 2.2737x; 1.2149x over previous
#include <cuda_runtime.h>
#include <cstdint>
#include <cstddef>

#define NUc 100000
#define NTc 200000
#define Ec  1000000

typedef unsigned long long u64;
typedef unsigned int u32;

// ---------------- scratch (device globals; no allocation) ----------------
__device__ __align__(128) float g_hu [NUc*64];
__device__ __align__(128) float g_ht [NTc*64];
__device__ __align__(128) float g_mu0[NUc*64];   // (hu@W_u2u) * d_u2u[row]
__device__ __align__(128) float g_mu1[NUc*64];   // (hu@W_u2t) * ds_u2t[row]
__device__ __align__(128) float g_mt0[NTc*64];   // (ht@W_t2t) * d_t2t[row]
__device__ __align__(128) float g_mt1[NTc*64];   // (ht@W_t2u) * ds_t2u[row]

__device__ int g_c_u2u[NUc];
__device__ int g_c_t2t[NTc];
__device__ int g_c_u2t_d[NTc];
__device__ int g_c_t2u_d[NUc];
__device__ int g_c_u2t_s[NUc];
__device__ int g_c_t2u_s[NTc];

__device__ float g_d_u2u[NUc];    // rsqrt(deg+1) (incl self loop)
__device__ float g_d_t2t[NTc];
__device__ float g_ds_u2t[NUc];
__device__ float g_dd_u2t[NTc];
__device__ float g_ds_t2u[NTc];
__device__ float g_dd_t2u[NUc];

__device__ int g_off_u2u[NUc+1];
__device__ int g_off_t2t[NTc+1];
__device__ int g_off_u2t[NTc+1];
__device__ int g_off_t2u[NUc+1];
__device__ int g_cur_u2u[NUc];
__device__ int g_cur_t2t[NTc];
__device__ int g_cur_u2t[NTc];
__device__ int g_cur_t2u[NUc];
__device__ int g_csr_u2u[Ec];
__device__ int g_csr_t2t[Ec];
__device__ int g_csr_u2t[Ec];
__device__ int g_csr_t2u[Ec];

__device__ float g_colsum[128];

// ---------------- helpers ----------------
__device__ __forceinline__ u32 f2tf(float f) {
    u32 u; asm("cvt.rna.tf32.f32 %0,%1;" : "=r"(u) : "f"(f)); return u;
}
__device__ __forceinline__ void mma_tf32(float* c, u32 a0, u32 a1, u32 a2, u32 a3,
                                         u32 b0, u32 b1) {
    asm volatile(
        "mma.sync.aligned.m16n8k8.row.col.f32.tf32.tf32.f32 "
        "{%0,%1,%2,%3}, {%4,%5,%6,%7}, {%8,%9}, {%0,%1,%2,%3};"
        : "+f"(c[0]), "+f"(c[1]), "+f"(c[2]), "+f"(c[3])
        : "r"(a0), "r"(a1), "r"(a2), "r"(a3), "r"(b0), "r"(b1));
}

// ---------------- setup: counts ----------------
__global__ void zero_cnt_kernel() {
    int i = blockIdx.x * blockDim.x + threadIdx.x;
    if (i < NUc) { g_c_u2u[i] = 0; g_c_u2t_s[i] = 0; g_c_t2u_d[i] = 0; }
    if (i < NTc) { g_c_t2t[i] = 0; g_c_u2t_d[i] = 0; g_c_t2u_s[i] = 0; }
    if (i < 128) g_colsum[i] = 0.f;
}

__global__ void count_kernel(const int* __restrict__ eu2u, const int* __restrict__ et2t,
                             const int* __restrict__ eu2t, const int* __restrict__ et2u) {
    int e = blockIdx.x * blockDim.x + threadIdx.x;
    if (e >= Ec) return;
    atomicAdd(&g_c_u2u[eu2u[Ec + e]], 1);
    atomicAdd(&g_c_t2t[et2t[Ec + e]], 1);
    atomicAdd(&g_c_u2t_d[eu2t[Ec + e]], 1);
    atomicAdd(&g_c_u2t_s[eu2t[e]],      1);
    atomicAdd(&g_c_t2u_d[et2u[Ec + e]], 1);
    atomicAdd(&g_c_t2u_s[et2u[e]],      1);
}

// ---------------- setup: 4 exclusive scans (one block each) ----------------
__global__ void scan4_kernel() {
    const int* cnt; int* off; int* cur; int n;
    switch (blockIdx.x) {
        case 0:  cnt = g_c_u2u;   off = g_off_u2u; cur = g_cur_u2u; n = NUc; break;
        case 1:  cnt = g_c_t2t;   off = g_off_t2t; cur = g_cur_t2t; n = NTc; break;
        case 2:  cnt = g_c_u2t_d; off = g_off_u2t; cur = g_cur_u2t; n = NTc; break;
        default: cnt = g_c_t2u_d; off = g_off_t2u; cur = g_cur_t2u; n = NUc; break;
    }
    __shared__ int sh[1024];
    int tid = threadIdx.x;
    int chunk = (n + 1023) >> 10;
    int start = tid * chunk;
    int end = min(start + chunk, n);
    int s = 0;
    for (int i = start; i < end; i++) s += cnt[i];
    sh[tid] = s;
    __syncthreads();
    for (int d = 1; d < 1024; d <<= 1) {
        int v = (tid >= d) ? sh[tid - d] : 0;
        __syncthreads();
        sh[tid] += v;
        __syncthreads();
    }
    int run = sh[tid] - s;   // exclusive prefix of this chunk
    for (int i = start; i < end; i++) { off[i] = run; cur[i] = run; run += cnt[i]; }
    if (start < n && end == n) off[n] = run;
}

// ---------------- setup: CSR fill ----------------
__global__ void fill_kernel(const int* __restrict__ eu2u, const int* __restrict__ et2t,
                            const int* __restrict__ eu2t, const int* __restrict__ et2u) {
    int e = blockIdx.x * blockDim.x + threadIdx.x;
    if (e >= Ec) return;
    int p;
    p = atomicAdd(&g_cur_u2u[eu2u[Ec + e]], 1); g_csr_u2u[p] = eu2u[e];
    p = atomicAdd(&g_cur_t2t[et2t[Ec + e]], 1); g_csr_t2t[p] = et2t[e];
    p = atomicAdd(&g_cur_u2t[eu2t[Ec + e]], 1); g_csr_u2t[p] = eu2t[e];
    p = atomicAdd(&g_cur_t2u[et2u[Ec + e]], 1); g_csr_t2u[p] = et2u[e];
}

__global__ void dinv_kernel() {
    int i = blockIdx.x * blockDim.x + threadIdx.x;
    if (i < NUc) {
        g_d_u2u[i] = rsqrtf((float)g_c_u2u[i] + 1.f);
        int cs = g_c_u2t_s[i]; g_ds_u2t[i] = (cs > 0) ? rsqrtf((float)cs) : 0.f;
        int cd = g_c_t2u_d[i]; g_dd_t2u[i] = (cd > 0) ? rsqrtf((float)cd) : 0.f;
    }
    if (i < NTc) {
        g_d_t2t[i] = rsqrtf((float)g_c_t2t[i] + 1.f);
        int cd = g_c_u2t_d[i]; g_dd_u2t[i] = (cd > 0) ? rsqrtf((float)cd) : 0.f;
        int cs = g_c_t2u_s[i]; g_ds_t2u[i] = (cs > 0) ? rsqrtf((float)cs) : 0.f;
    }
}

// ---------------- tf32 tensor-core GEMM: 128 rows/block, K=64, N=64 ----------------
// smem layout (floats): Wf0[4096] (frag-ordered), [Wf1[4096] if DUAL], As/staging[128*72]
// Wf layout: f = ((kk*8 + nt)*32 + lane)  ->  float2 { B[kk*8+k0][nt*8+n], B[kk*8+k0+4][nt*8+n] }
//            with k0 = lane&3, n = lane>>2.  (one conflict-free LDS.64 per fragment)
// As pitch 72 (A-frag LDS ~conflict-free, float4-aligned).
template<bool DUAL, bool BIAS>
__device__ __forceinline__ void mma_gemm64(const float* __restrict__ A,
                                           const float* __restrict__ W0,
                                           const float* __restrict__ W1,
                                           const float* __restrict__ sc0,
                                           const float* __restrict__ sc1,
                                           const float* __restrict__ bias,
                                           float* __restrict__ O0,
                                           float* __restrict__ O1, int N) {
    extern __shared__ float sm[];
    float* Wf0 = sm;
    float* Wf1 = DUAL ? (sm + 4096) : sm;
    float* As  = sm + (DUAL ? 8192 : 4096);   // 128*72 floats; reused as staging
    int t = threadIdx.x;
    int lane = t & 31, wid = t >> 5;
    int row0 = blockIdx.x * 128;

    // pack weight fragments
    for (int i = t; i < 2048; i += 256) {
        int kk = i >> 8, rem = i & 255;
        int nt = rem >> 5, ln = rem & 31;
        int k0 = ln & 3, n = ln >> 2;
        int col = nt * 8 + n, k = kk * 8 + k0;
        float2 v;
        v.x = __uint_as_float(f2tf(W0[k * 64 + col]));
        v.y = __uint_as_float(f2tf(W0[(k + 4) * 64 + col]));
        *(float2*)&Wf0[(size_t)i * 2] = v;
        if (DUAL) {
            v.x = __uint_as_float(f2tf(W1[k * 64 + col]));
            v.y = __uint_as_float(f2tf(W1[(k + 4) * 64 + col]));
            *(float2*)&Wf1[(size_t)i * 2] = v;
        }
    }
    // load + convert A tile
    for (int i = t; i < 128 * 64; i += 256) {
        int r = i >> 6, c = i & 63;
        int gr = row0 + r;
        float v = (gr < N) ? A[((size_t)gr << 6) + c] : 0.f;
        As[r * 72 + c] = __uint_as_float(f2tf(v));
    }
    __syncthreads();

    const u32* Asu = (const u32*)As;
    int rbase = wid * 16;
    int fr = lane >> 2, fc = lane & 3;

    float acc0[8][4];
    float acc1[DUAL ? 8 : 1][4];
#pragma unroll
    for (int nt = 0; nt < 8; nt++)
#pragma unroll
        for (int j = 0; j < 4; j++) { acc0[nt][j] = 0.f; if (DUAL) acc1[nt][j] = 0.f; }

#pragma unroll
    for (int kk = 0; kk < 8; kk++) {
        int base = (rbase + fr) * 72 + kk * 8 + fc;
        u32 a0 = Asu[base];
        u32 a1 = Asu[base + 8 * 72];
        u32 a2 = Asu[base + 4];
        u32 a3 = Asu[base + 8 * 72 + 4];
#pragma unroll
        for (int nt = 0; nt < 8; nt++) {
            float2 b = *(const float2*)&Wf0[(size_t)(((kk << 3) + nt) << 5 | lane) * 2];
            mma_tf32(acc0[nt], a0, a1, a2, a3, __float_as_uint(b.x), __float_as_uint(b.y));
            if (DUAL) {
                float2 c = *(const float2*)&Wf1[(size_t)(((kk << 3) + nt) << 5 | lane) * 2];
                mma_tf32(acc1[nt], a0, a1, a2, a3, __float_as_uint(c.x), __float_as_uint(c.y));
            }
        }
    }

    // ---- epilogue: stage D through smem, coalesced stores ----
    float* st = As;
    __syncthreads();
#pragma unroll
    for (int nt = 0; nt < 8; nt++) {
        int cbase = nt * 8 + fc * 2;
        *(float2*)&st[(rbase + fr) * 72 + cbase]     = make_float2(acc0[nt][0], acc0[nt][1]);
        *(float2*)&st[(rbase + fr + 8) * 72 + cbase] = make_float2(acc0[nt][2], acc0[nt][3]);
    }
    __syncthreads();
    for (int i = t; i < 128 * 16; i += 256) {
        int r = i >> 4, c4 = (i & 15) << 2;
        int gr = row0 + r;
        if (gr < N) {
            float4 v = *(float4*)&st[r * 72 + c4];
            if (BIAS) {
                float4 bv = *(const float4*)(bias + c4);
                v.x += bv.x; v.y += bv.y; v.z += bv.z; v.w += bv.w;
            } else {
                float s = sc0[gr];
                v.x *= s; v.y *= s; v.z *= s; v.w *= s;
            }
            *(float4*)&O0[((size_t)gr << 6) + c4] = v;
        }
    }
    if (DUAL) {
        __syncthreads();
#pragma unroll
        for (int nt = 0; nt < 8; nt++) {
            int cbase = nt * 8 + fc * 2;
            *(float2*)&st[(rbase + fr) * 72 + cbase]     = make_float2(acc1[nt][0], acc1[nt][1]);
            *(float2*)&st[(rbase + fr + 8) * 72 + cbase] = make_float2(acc1[nt][2], acc1[nt][3]);
        }
        __syncthreads();
        for (int i = t; i < 128 * 16; i += 256) {
            int r = i >> 4, c4 = (i & 15) << 2;
            int gr = row0 + r;
            if (gr < N) {
                float4 v = *(float4*)&st[r * 72 + c4];
                float s = sc1[gr];
                v.x *= s; v.y *= s; v.z *= s; v.w *= s;
                *(float4*)&O1[((size_t)gr << 6) + c4] = v;
            }
        }
    }
}

__global__ void __launch_bounds__(256) transform_u_kernel(const float* __restrict__ W0,
                                                          const float* __restrict__ W1) {
    mma_gemm64<true, false>(g_hu, W0, W1, g_d_u2u, g_ds_u2t, nullptr, g_mu0, g_mu1, NUc);
}
__global__ void __launch_bounds__(256) transform_t_kernel(const float* __restrict__ W0,
                                                          const float* __restrict__ W1) {
    mma_gemm64<true, false>(g_ht, W0, W1, g_d_t2t, g_ds_t2u, nullptr, g_mt0, g_mt1, NTc);
}
__global__ void __launch_bounds__(256) embed_txn_kernel(const float* __restrict__ x,
                                                        const float* __restrict__ W,
                                                        const float* __restrict__ b) {
    mma_gemm64<false, true>(x, W, nullptr, nullptr, nullptr, b, g_ht, nullptr, NTc);
}

// ---------------- fp32 embed for K=32 (small, one-time) ----------------
__global__ void __launch_bounds__(256) embed_user_kernel(const float* __restrict__ A,
                                                         const float* __restrict__ W,
                                                         const float* __restrict__ b) {
    const int K = 32;
    __shared__ float Ws[K * 64];
    __shared__ float As[32 * (K + 1)];
    int t = threadIdx.x;
    for (int i = t; i < K * 64; i += 256) Ws[i] = W[i];
    int row0 = blockIdx.x * 32;
    for (int i = t; i < 32 * K; i += 256) {
        int r = i / K, c = i - r * K; int gr = row0 + r;
        As[r * (K + 1) + c] = (gr < NUc) ? A[(size_t)gr * K + c] : 0.f;
    }
    __syncthreads();
    int r = t >> 3, cseg = (t & 7) << 3;
    float acc[8];
#pragma unroll
    for (int i = 0; i < 8; i++) acc[i] = b[cseg + i];
#pragma unroll
    for (int k = 0; k < K; k++) {
        float a = As[r * (K + 1) + k];
#pragma unroll
        for (int i = 0; i < 8; i++) acc[i] += a * Ws[(k << 6) + cseg + i];
    }
    int gr = row0 + r;
    if (gr < NUc) {
        float4* p = (float4*)(g_hu + ((size_t)gr << 6) + cseg);
        p[0] = make_float4(acc[0], acc[1], acc[2], acc[3]);
        p[1] = make_float4(acc[4], acc[5], acc[6], acc[7]);
    }
}

// ---------------- fused gather-aggregate + bias + relu (no atomics) ----------------
__global__ void __launch_bounds__(256) agg_u_kernel(const float* __restrict__ bA,
                                                    const float* __restrict__ bB) {
    int idx = blockIdx.x * 256 + threadIdx.x;
    int g = idx >> 3;
    if (g >= NUc) return;
    int c0 = (idx & 7) << 3;
    const float4* sp = (const float4*)(g_mu0 + ((size_t)g << 6) + c0);
    float4 a0 = __ldg(sp), a1 = __ldg(sp + 1);
    int e = g_off_u2u[g], end = g_off_u2u[g + 1];
    for (; e < end; e++) {
        int s = g_csr_u2u[e];
        const float4* p = (const float4*)(g_mu0 + ((size_t)s << 6) + c0);
        float4 v0 = __ldg(p), v1 = __ldg(p + 1);
        a0.x += v0.x; a0.y += v0.y; a0.z += v0.z; a0.w += v0.w;
        a1.x += v1.x; a1.y += v1.y; a1.z += v1.z; a1.w += v1.w;
    }
    float du = g_d_u2u[g];
    float4 b0 = make_float4(0.f, 0.f, 0.f, 0.f), b1 = b0;
    e = g_off_t2u[g]; end = g_off_t2u[g + 1];
    for (; e < end; e++) {
        int s = g_csr_t2u[e];
        const float4* p = (const float4*)(g_mt1 + ((size_t)s << 6) + c0);
        float4 v0 = __ldg(p), v1 = __ldg(p + 1);
        b0.x += v0.x; b0.y += v0.y; b0.z += v0.z; b0.w += v0.w;
        b1.x += v1.x; b1.y += v1.y; b1.z += v1.z; b1.w += v1.w;
    }
    float dt = g_dd_t2u[g];
    float4 bAv0 = __ldg((const float4*)(bA + c0)), bAv1 = __ldg((const float4*)(bA + c0 + 4));
    float4 bBv0 = __ldg((const float4*)(bB + c0)), bBv1 = __ldg((const float4*)(bB + c0 + 4));
    float4 o0, o1;
    o0.x = fmaxf(0.5f * (du * a0.x + dt * b0.x + bAv0.x + bBv0.x), 0.f);
    o0.y = fmaxf(0.5f * (du * a0.y + dt * b0.y + bAv0.y + bBv0.y), 0.f);
    o0.z = fmaxf(0.5f * (du * a0.z + dt * b0.z + bAv0.z + bBv0.z), 0.f);
    o0.w = fmaxf(0.5f * (du * a0.w + dt * b0.w + bAv0.w + bBv0.w), 0.f);
    o1.x = fmaxf(0.5f * (du * a1.x + dt * b1.x + bAv1.x + bBv1.x), 0.f);
    o1.y = fmaxf(0.5f * (du * a1.y + dt * b1.y + bAv1.y + bBv1.y), 0.f);
    o1.z = fmaxf(0.5f * (du * a1.z + dt * b1.z + bAv1.z + bBv1.z), 0.f);
    o1.w = fmaxf(0.5f * (du * a1.w + dt * b1.w + bAv1.w + bBv1.w), 0.f);
    float4* op = (float4*)(g_hu + ((size_t)g << 6) + c0);
    op[0] = o0; op[1] = o1;
}

__global__ void __launch_bounds__(256) agg_t_kernel(const float* __restrict__ bA,
                                                    const float* __restrict__ bB) {
    int idx = blockIdx.x * 256 + threadIdx.x;
    int g = idx >> 3;
    if (g >= NTc) return;
    int c0 = (idx & 7) << 3;
    const float4* sp = (const float4*)(g_mt0 + ((size_t)g << 6) + c0);
    float4 a0 = __ldg(sp), a1 = __ldg(sp + 1);
    int e = g_off_t2t[g], end = g_off_t2t[g + 1];
    for (; e < end; e++) {
        int s = g_csr_t2t[e];
        const float4* p = (const float4*)(g_mt0 + ((size_t)s << 6) + c0);
        float4 v0 = __ldg(p), v1 = __ldg(p + 1);
        a0.x += v0.x; a0.y += v0.y; a0.z += v0.z; a0.w += v0.w;
        a1.x += v1.x; a1.y += v1.y; a1.z += v1.z; a1.w += v1.w;
    }
    float du = g_d_t2t[g];
    float4 b0 = make_float4(0.f, 0.f, 0.f, 0.f), b1 = b0;
    e = g_off_u2t[g]; end = g_off_u2t[g + 1];
    for (; e < end; e++) {
        int s = g_csr_u2t[e];
        const float4* p = (const float4*)(g_mu1 + ((size_t)s << 6) + c0);
        float4 v0 = __ldg(p), v1 = __ldg(p + 1);
        b0.x += v0.x; b0.y += v0.y; b0.z += v0.z; b0.w += v0.w;
        b1.x += v1.x; b1.y += v1.y; b1.z += v1.z; b1.w += v1.w;
    }
    float dt = g_dd_u2t[g];
    float4 bAv0 = __ldg((const float4*)(bA + c0)), bAv1 = __ldg((const float4*)(bA + c0 + 4));
    float4 bBv0 = __ldg((const float4*)(bB + c0)), bBv1 = __ldg((const float4*)(bB + c0 + 4));
    float4 o0, o1;
    o0.x = fmaxf(0.5f * (du * a0.x + dt * b0.x + bAv0.x + bBv0.x), 0.f);
    o0.y = fmaxf(0.5f * (du * a0.y + dt * b0.y + bAv0.y + bBv0.y), 0.f);
    o0.z = fmaxf(0.5f * (du * a0.z + dt * b0.z + bAv0.z + bBv0.z), 0.f);
    o0.w = fmaxf(0.5f * (du * a0.w + dt * b0.w + bAv0.w + bBv0.w), 0.f);
    o1.x = fmaxf(0.5f * (du * a1.x + dt * b1.x + bAv1.x + bBv1.x), 0.f);
    o1.y = fmaxf(0.5f * (du * a1.y + dt * b1.y + bAv1.y + bBv1.y), 0.f);
    o1.z = fmaxf(0.5f * (du * a1.z + dt * b1.z + bAv1.z + bBv1.z), 0.f);
    o1.w = fmaxf(0.5f * (du * a1.w + dt * b1.w + bAv1.w + bBv1.w), 0.f);
    float4* op = (float4*)(g_ht + ((size_t)g << 6) + c0);
    op[0] = o0; op[1] = o1;
}

// ---------------- readout ----------------
#define CS_BLOCKS 296
__global__ void colsum_u_kernel() {
    int t = blockIdx.x * blockDim.x + threadIdx.x;
    float s = 0.f;
    const int n = NUc * 64;
    for (int i = t; i < n; i += CS_BLOCKS * 256) s += g_hu[i];
    atomicAdd(&g_colsum[t & 63], s);
}
__global__ void colsum_t_kernel() {
    int t = blockIdx.x * blockDim.x + threadIdx.x;
    float s = 0.f;
    const int n = NTc * 64;
    for (int i = t; i < n; i += CS_BLOCKS * 256) s += g_ht[i];
    atomicAdd(&g_colsum[64 + (t & 63)], s);
}

__global__ void mlp_kernel(const float* __restrict__ W1, const float* __restrict__ b1,
                           const float* __restrict__ W2, const float* __restrict__ b2,
                           float* __restrict__ out) {
    __shared__ float x[64];
    __shared__ float y[64];
    int t = threadIdx.x;
    x[t] = 0.5f * (g_colsum[t] * (1.f / NUc) + g_colsum[64 + t] * (1.f / NTc));
    __syncthreads();
    float s = b1[t];
    for (int k = 0; k < 64; k++) s += x[k] * W1[k * 64 + t];
    y[t] = fmaxf(s, 0.f) * W2[t];
    __syncthreads();
    if (t == 0) {
        float o = b2[0];
        for (int j = 0; j < 64; j++) o += y[j];
        out[0] = 1.f / (1.f + expf(-o));
    }
}

// ---------------- launch ----------------
extern "C" void kernel_launch(void* const* d_in, const int* in_sizes, int n_in,
                              void* d_out, int out_size) {
    const float* x_user     = (const float*)d_in[0];
    const float* x_txn      = (const float*)d_in[1];
    const int*   ei_u2u     = (const int*)d_in[2];
    const int*   ei_t2t     = (const int*)d_in[3];
    const int*   ei_u2t     = (const int*)d_in[4];
    const int*   ei_t2u     = (const int*)d_in[5];
    const float* W_emb_user = (const float*)d_in[6];
    const float* b_emb_user = (const float*)d_in[7];
    const float* W_emb_txn  = (const float*)d_in[8];
    const float* b_emb_txn  = (const float*)d_in[9];
    const float* conv_W     = (const float*)d_in[10];
    const float* conv_b     = (const float*)d_in[11];
    const float* W1         = (const float*)d_in[12];
    const float* b1         = (const float*)d_in[13];
    const float* W2         = (const float*)d_in[14];
    const float* b2         = (const float*)d_in[15];
    float* out = (float*)d_out;

    const int SMEM_DUAL = (2 * 4096 + 128 * 72) * 4;   // 69632
    const int SMEM_SNGL = (4096 + 128 * 72) * 4;       // 53248
    cudaFuncSetAttribute(transform_u_kernel, cudaFuncAttributeMaxDynamicSharedMemorySize, SMEM_DUAL);
    cudaFuncSetAttribute(transform_t_kernel, cudaFuncAttributeMaxDynamicSharedMemorySize, SMEM_DUAL);
    cudaFuncSetAttribute(embed_txn_kernel, cudaFuncAttributeMaxDynamicSharedMemorySize, SMEM_SNGL);

    // ---- CSR + norms (edge structure is layer-invariant) ----
    zero_cnt_kernel<<<(NTc + 255) / 256, 256>>>();
    count_kernel<<<(Ec + 255) / 256, 256>>>(ei_u2u, ei_t2t, ei_u2t, ei_t2u);
    scan4_kernel<<<4, 1024>>>();
    fill_kernel<<<(Ec + 255) / 256, 256>>>(ei_u2u, ei_t2t, ei_u2t, ei_t2u);
    dinv_kernel<<<(NTc + 255) / 256, 256>>>();

    // ---- embeddings ----
    embed_user_kernel<<<(NUc + 31) / 32, 256>>>(x_user, W_emb_user, b_emb_user);
    embed_txn_kernel<<<(NTc + 127) / 128, 256, SMEM_SNGL>>>(x_txn, W_emb_txn, b_emb_txn);

    // ---- layers ----
    for (int l = 0; l < 3; l++) {
        const float* W = conv_W + (size_t)l * 4 * 64 * 64;
        const float* B = conv_b + (size_t)l * 4 * 64;
        transform_u_kernel<<<(NUc + 127) / 128, 256, SMEM_DUAL>>>(W + 0 * 4096, W + 2 * 4096);
        transform_t_kernel<<<(NTc + 127) / 128, 256, SMEM_DUAL>>>(W + 1 * 4096, W + 3 * 4096);
        agg_u_kernel<<<(NUc * 8 + 255) / 256, 256>>>(B + 0 * 64, B + 3 * 64);
        agg_t_kernel<<<(NTc * 8 + 255) / 256, 256>>>(B + 1 * 64, B + 2 * 64);
    }

    // ---- readout ----
    colsum_u_kernel<<<CS_BLOCKS, 256>>>();
    colsum_t_kernel<<<CS_BLOCKS, 256>>>();
    mlp_kernel<<<1, 64>>>(W1, b1, W2, b2, out);
}

// round 4
// speedup vs baseline: 2.7114x; 1.1925x over previous
#include <cuda_runtime.h>
#include <cuda_fp16.h>
#include <cstdint>
#include <cstddef>

#define NUc 100000
#define NTc 200000
#define Ec  1000000

typedef unsigned long long u64;
typedef unsigned int u32;

// ---------------- scratch (device globals; no allocation) ----------------
__device__ __align__(128) float g_hu [NUc*64];
__device__ __align__(128) float g_ht [NTc*64];
// transformed messages, fp16 packed (half2 pairs), row = 32 u32
__device__ __align__(128) u32 g_mu0h[NUc*32];   // (hu@W_u2u) * d_u2u[row]
__device__ __align__(128) u32 g_mu1h[NUc*32];   // (hu@W_u2t) * ds_u2t[row]
__device__ __align__(128) u32 g_mt0h[NTc*32];   // (ht@W_t2t) * d_t2t[row]
__device__ __align__(128) u32 g_mt1h[NTc*32];   // (ht@W_t2u) * ds_t2u[row]

__device__ int g_c_u2u[NUc];
__device__ int g_c_t2t[NTc];
__device__ int g_c_u2t_d[NTc];
__device__ int g_c_t2u_d[NUc];
__device__ int g_c_u2t_s[NUc];
__device__ int g_c_t2u_s[NTc];

__device__ float g_d_u2u[NUc];    // rsqrt(deg+1) (incl self loop)
__device__ float g_d_t2t[NTc];
__device__ float g_ds_u2t[NUc];
__device__ float g_dd_u2t[NTc];
__device__ float g_ds_t2u[NTc];
__device__ float g_dd_t2u[NUc];

__device__ int g_off_u2u[NUc+1];
__device__ int g_off_t2t[NTc+1];
__device__ int g_off_u2t[NTc+1];
__device__ int g_off_t2u[NUc+1];
__device__ int g_cur_u2u[NUc];
__device__ int g_cur_t2t[NTc];
__device__ int g_cur_u2t[NTc];
__device__ int g_cur_t2u[NUc];
__device__ int g_csr_u2u[Ec];
__device__ int g_csr_t2t[Ec];
__device__ int g_csr_u2t[Ec];
__device__ int g_csr_t2u[Ec];

__device__ float g_colsum[128];

// ---------------- helpers ----------------
__device__ __forceinline__ u32 f2tf(float f) {
    u32 u; asm("cvt.rna.tf32.f32 %0,%1;" : "=r"(u) : "f"(f)); return u;
}
__device__ __forceinline__ void mma_tf32(float* c, u32 a0, u32 a1, u32 a2, u32 a3,
                                         u32 b0, u32 b1) {
    asm volatile(
        "mma.sync.aligned.m16n8k8.row.col.f32.tf32.tf32.f32 "
        "{%0,%1,%2,%3}, {%4,%5,%6,%7}, {%8,%9}, {%0,%1,%2,%3};"
        : "+f"(c[0]), "+f"(c[1]), "+f"(c[2]), "+f"(c[3])
        : "r"(a0), "r"(a1), "r"(a2), "r"(a3), "r"(b0), "r"(b1));
}
__device__ __forceinline__ void acc_h8(float* acc, uint4 v) {
    float2 f;
    f = __half22float2(*(__half2*)&v.x); acc[0] += f.x; acc[1] += f.y;
    f = __half22float2(*(__half2*)&v.y); acc[2] += f.x; acc[3] += f.y;
    f = __half22float2(*(__half2*)&v.z); acc[4] += f.x; acc[5] += f.y;
    f = __half22float2(*(__half2*)&v.w); acc[6] += f.x; acc[7] += f.y;
}

// ---------------- setup: counts ----------------
__global__ void zero_cnt_kernel() {
    int i = blockIdx.x * blockDim.x + threadIdx.x;
    if (i < NUc) { g_c_u2u[i] = 0; g_c_u2t_s[i] = 0; g_c_t2u_d[i] = 0; }
    if (i < NTc) { g_c_t2t[i] = 0; g_c_u2t_d[i] = 0; g_c_t2u_s[i] = 0; }
    if (i < 128) g_colsum[i] = 0.f;
}

__global__ void count_kernel(const int* __restrict__ eu2u, const int* __restrict__ et2t,
                             const int* __restrict__ eu2t, const int* __restrict__ et2u) {
    int e = blockIdx.x * blockDim.x + threadIdx.x;
    if (e >= Ec) return;
    atomicAdd(&g_c_u2u[eu2u[Ec + e]], 1);
    atomicAdd(&g_c_t2t[et2t[Ec + e]], 1);
    atomicAdd(&g_c_u2t_d[eu2t[Ec + e]], 1);
    atomicAdd(&g_c_u2t_s[eu2t[e]],      1);
    atomicAdd(&g_c_t2u_d[et2u[Ec + e]], 1);
    atomicAdd(&g_c_t2u_s[et2u[e]],      1);
}

// ---------------- setup: 4 exclusive scans (one block each) ----------------
__global__ void scan4_kernel() {
    const int* cnt; int* off; int* cur; int n;
    switch (blockIdx.x) {
        case 0:  cnt = g_c_u2u;   off = g_off_u2u; cur = g_cur_u2u; n = NUc; break;
        case 1:  cnt = g_c_t2t;   off = g_off_t2t; cur = g_cur_t2t; n = NTc; break;
        case 2:  cnt = g_c_u2t_d; off = g_off_u2t; cur = g_cur_u2t; n = NTc; break;
        default: cnt = g_c_t2u_d; off = g_off_t2u; cur = g_cur_t2u; n = NUc; break;
    }
    __shared__ int sh[1024];
    int tid = threadIdx.x;
    int chunk = (n + 1023) >> 10;
    int start = tid * chunk;
    int end = min(start + chunk, n);
    int s = 0;
    for (int i = start; i < end; i++) s += cnt[i];
    sh[tid] = s;
    __syncthreads();
    for (int d = 1; d < 1024; d <<= 1) {
        int v = (tid >= d) ? sh[tid - d] : 0;
        __syncthreads();
        sh[tid] += v;
        __syncthreads();
    }
    int run = sh[tid] - s;   // exclusive prefix of this chunk
    for (int i = start; i < end; i++) { off[i] = run; cur[i] = run; run += cnt[i]; }
    if (start < n && end == n) off[n] = run;
}

// ---------------- setup: CSR fill ----------------
__global__ void fill_kernel(const int* __restrict__ eu2u, const int* __restrict__ et2t,
                            const int* __restrict__ eu2t, const int* __restrict__ et2u) {
    int e = blockIdx.x * blockDim.x + threadIdx.x;
    if (e >= Ec) return;
    int p;
    p = atomicAdd(&g_cur_u2u[eu2u[Ec + e]], 1); g_csr_u2u[p] = eu2u[e];
    p = atomicAdd(&g_cur_t2t[et2t[Ec + e]], 1); g_csr_t2t[p] = et2t[e];
    p = atomicAdd(&g_cur_u2t[eu2t[Ec + e]], 1); g_csr_u2t[p] = eu2t[e];
    p = atomicAdd(&g_cur_t2u[et2u[Ec + e]], 1); g_csr_t2u[p] = et2u[e];
}

__global__ void dinv_kernel() {
    int i = blockIdx.x * blockDim.x + threadIdx.x;
    if (i < NUc) {
        g_d_u2u[i] = rsqrtf((float)g_c_u2u[i] + 1.f);
        int cs = g_c_u2t_s[i]; g_ds_u2t[i] = (cs > 0) ? rsqrtf((float)cs) : 0.f;
        int cd = g_c_t2u_d[i]; g_dd_t2u[i] = (cd > 0) ? rsqrtf((float)cd) : 0.f;
    }
    if (i < NTc) {
        g_d_t2t[i] = rsqrtf((float)g_c_t2t[i] + 1.f);
        int cd = g_c_u2t_d[i]; g_dd_u2t[i] = (cd > 0) ? rsqrtf((float)cd) : 0.f;
        int cs = g_c_t2u_s[i]; g_ds_t2u[i] = (cs > 0) ? rsqrtf((float)cs) : 0.f;
    }
}

// ---------------- tf32 tensor-core GEMM core: 128-row tile, K=64, N=64 ----------------
// DUAL: two weight matrices, outputs scaled by per-row sc, written fp16-packed.
// !DUAL (BIAS): single weights + bias, written fp32.
template<bool DUAL>
__device__ __forceinline__ void mma_gemm64(const float* __restrict__ A,
                                           const float* __restrict__ W0,
                                           const float* __restrict__ W1,
                                           const float* __restrict__ sc0,
                                           const float* __restrict__ sc1,
                                           const float* __restrict__ bias,
                                           u32* __restrict__ O0h,
                                           u32* __restrict__ O1h,
                                           float* __restrict__ O0f,
                                           int N, int tile) {
    extern __shared__ float sm[];
    float* Wf0 = sm;
    float* Wf1 = DUAL ? (sm + 4096) : sm;
    float* As  = sm + (DUAL ? 8192 : 4096);   // 128*72 floats; reused as staging
    int t = threadIdx.x;
    int lane = t & 31, wid = t >> 5;
    int row0 = tile * 128;

    // pack weight fragments
    for (int i = t; i < 2048; i += 256) {
        int kk = i >> 8, rem = i & 255;
        int nt = rem >> 5, ln = rem & 31;
        int k0 = ln & 3, n = ln >> 2;
        int col = nt * 8 + n, k = kk * 8 + k0;
        float2 v;
        v.x = __uint_as_float(f2tf(W0[k * 64 + col]));
        v.y = __uint_as_float(f2tf(W0[(k + 4) * 64 + col]));
        *(float2*)&Wf0[(size_t)i * 2] = v;
        if (DUAL) {
            v.x = __uint_as_float(f2tf(W1[k * 64 + col]));
            v.y = __uint_as_float(f2tf(W1[(k + 4) * 64 + col]));
            *(float2*)&Wf1[(size_t)i * 2] = v;
        }
    }
    // load + convert A tile
    for (int i = t; i < 128 * 64; i += 256) {
        int r = i >> 6, c = i & 63;
        int gr = row0 + r;
        float v = (gr < N) ? A[((size_t)gr << 6) + c] : 0.f;
        As[r * 72 + c] = __uint_as_float(f2tf(v));
    }
    __syncthreads();

    const u32* Asu = (const u32*)As;
    int rbase = wid * 16;
    int fr = lane >> 2, fc = lane & 3;

    float acc0[8][4];
    float acc1[DUAL ? 8 : 1][4];
#pragma unroll
    for (int nt = 0; nt < 8; nt++)
#pragma unroll
        for (int j = 0; j < 4; j++) { acc0[nt][j] = 0.f; if (DUAL) acc1[nt][j] = 0.f; }

#pragma unroll
    for (int kk = 0; kk < 8; kk++) {
        int base = (rbase + fr) * 72 + kk * 8 + fc;
        u32 a0 = Asu[base];
        u32 a1 = Asu[base + 8 * 72];
        u32 a2 = Asu[base + 4];
        u32 a3 = Asu[base + 8 * 72 + 4];
#pragma unroll
        for (int nt = 0; nt < 8; nt++) {
            float2 b = *(const float2*)&Wf0[(size_t)(((kk << 3) + nt) << 5 | lane) * 2];
            mma_tf32(acc0[nt], a0, a1, a2, a3, __float_as_uint(b.x), __float_as_uint(b.y));
            if (DUAL) {
                float2 c = *(const float2*)&Wf1[(size_t)(((kk << 3) + nt) << 5 | lane) * 2];
                mma_tf32(acc1[nt], a0, a1, a2, a3, __float_as_uint(c.x), __float_as_uint(c.y));
            }
        }
    }

    // ---- epilogue: stage D through smem, coalesced stores ----
    float* st = As;
    __syncthreads();
#pragma unroll
    for (int nt = 0; nt < 8; nt++) {
        int cbase = nt * 8 + fc * 2;
        *(float2*)&st[(rbase + fr) * 72 + cbase]     = make_float2(acc0[nt][0], acc0[nt][1]);
        *(float2*)&st[(rbase + fr + 8) * 72 + cbase] = make_float2(acc0[nt][2], acc0[nt][3]);
    }
    __syncthreads();
    for (int i = t; i < 128 * 16; i += 256) {
        int r = i >> 4, c4 = (i & 15) << 2;
        int gr = row0 + r;
        if (gr < N) {
            float4 v = *(float4*)&st[r * 72 + c4];
            if (!DUAL) {
                float4 bv = *(const float4*)(bias + c4);
                v.x += bv.x; v.y += bv.y; v.z += bv.z; v.w += bv.w;
                *(float4*)&O0f[((size_t)gr << 6) + c4] = v;
            } else {
                float s = sc0[gr];
                __half2 h0 = __floats2half2_rn(v.x * s, v.y * s);
                __half2 h1 = __floats2half2_rn(v.z * s, v.w * s);
                uint2 pk;
                pk.x = *(u32*)&h0; pk.y = *(u32*)&h1;
                *(uint2*)&O0h[((size_t)gr << 5) + (c4 >> 1)] = pk;
            }
        }
    }
    if (DUAL) {
        __syncthreads();
#pragma unroll
        for (int nt = 0; nt < 8; nt++) {
            int cbase = nt * 8 + fc * 2;
            *(float2*)&st[(rbase + fr) * 72 + cbase]     = make_float2(acc1[nt][0], acc1[nt][1]);
            *(float2*)&st[(rbase + fr + 8) * 72 + cbase] = make_float2(acc1[nt][2], acc1[nt][3]);
        }
        __syncthreads();
        for (int i = t; i < 128 * 16; i += 256) {
            int r = i >> 4, c4 = (i & 15) << 2;
            int gr = row0 + r;
            if (gr < N) {
                float4 v = *(float4*)&st[r * 72 + c4];
                float s = sc1[gr];
                __half2 h0 = __floats2half2_rn(v.x * s, v.y * s);
                __half2 h1 = __floats2half2_rn(v.z * s, v.w * s);
                uint2 pk;
                pk.x = *(u32*)&h0; pk.y = *(u32*)&h1;
                *(uint2*)&O1h[((size_t)gr << 5) + (c4 >> 1)] = pk;
            }
        }
    }
}

#define GU_T ((NUc + 127) / 128)
#define GT_T ((NTc + 127) / 128)

// merged transforms for one layer: u tiles then t tiles
__global__ void __launch_bounds__(256) transform_kernel(const float* __restrict__ W) {
    int b = blockIdx.x;
    if (b < GU_T) {
        mma_gemm64<true>(g_hu, W + 0 * 4096, W + 2 * 4096, g_d_u2u, g_ds_u2t, nullptr,
                         g_mu0h, g_mu1h, nullptr, NUc, b);
    } else {
        mma_gemm64<true>(g_ht, W + 1 * 4096, W + 3 * 4096, g_d_t2t, g_ds_t2u, nullptr,
                         g_mt0h, g_mt1h, nullptr, NTc, b - GU_T);
    }
}

__global__ void __launch_bounds__(256) embed_txn_kernel(const float* __restrict__ x,
                                                        const float* __restrict__ W,
                                                        const float* __restrict__ b) {
    mma_gemm64<false>(x, W, nullptr, nullptr, nullptr, b, nullptr, nullptr, g_ht,
                      NTc, blockIdx.x);
}

// ---------------- fp32 embed for K=32 (small, one-time) ----------------
__global__ void __launch_bounds__(256) embed_user_kernel(const float* __restrict__ A,
                                                         const float* __restrict__ W,
                                                         const float* __restrict__ b) {
    const int K = 32;
    __shared__ float Ws[K * 64];
    __shared__ float As[32 * (K + 1)];
    int t = threadIdx.x;
    for (int i = t; i < K * 64; i += 256) Ws[i] = W[i];
    int row0 = blockIdx.x * 32;
    for (int i = t; i < 32 * K; i += 256) {
        int r = i / K, c = i - r * K; int gr = row0 + r;
        As[r * (K + 1) + c] = (gr < NUc) ? A[(size_t)gr * K + c] : 0.f;
    }
    __syncthreads();
    int r = t >> 3, cseg = (t & 7) << 3;
    float acc[8];
#pragma unroll
    for (int i = 0; i < 8; i++) acc[i] = b[cseg + i];
#pragma unroll
    for (int k = 0; k < K; k++) {
        float a = As[r * (K + 1) + k];
#pragma unroll
        for (int i = 0; i < 8; i++) acc[i] += a * Ws[(k << 6) + cseg + i];
    }
    int gr = row0 + r;
    if (gr < NUc) {
        float4* p = (float4*)(g_hu + ((size_t)gr << 6) + cseg);
        p[0] = make_float4(acc[0], acc[1], acc[2], acc[3]);
        p[1] = make_float4(acc[4], acc[5], acc[6], acc[7]);
    }
}

// ---------------- fused gather-aggregate + bias + relu (fp16 messages) ----------------
__device__ __forceinline__ void agg_body(int idx,
                                         const u32* __restrict__ mA,
                                         const int* __restrict__ offA,
                                         const int* __restrict__ csrA,
                                         const float* __restrict__ dA,
                                         const u32* __restrict__ mB,
                                         const int* __restrict__ offB,
                                         const int* __restrict__ csrB,
                                         const float* __restrict__ dB,
                                         const float* __restrict__ bA,
                                         const float* __restrict__ bB,
                                         float* __restrict__ Out, int N) {
    int g = idx >> 3;
    if (g >= N) return;
    int q = idx & 7;              // 8 columns per thread: one uint4 = 8 halves
    int woff = q << 2;            // u32 offset within row (row = 32 u32)
    float a[8], b[8];
    // self term (relation A includes self loop)
    {
        uint4 v = __ldg((const uint4*)(mA + ((size_t)g << 5) + woff));
        float2 f;
        f = __half22float2(*(__half2*)&v.x); a[0] = f.x; a[1] = f.y;
        f = __half22float2(*(__half2*)&v.y); a[2] = f.x; a[3] = f.y;
        f = __half22float2(*(__half2*)&v.z); a[4] = f.x; a[5] = f.y;
        f = __half22float2(*(__half2*)&v.w); a[6] = f.x; a[7] = f.y;
    }
#pragma unroll
    for (int i = 0; i < 8; i++) b[i] = 0.f;
    int e = offA[g], end = offA[g + 1];
    for (; e < end; e++) {
        int s = csrA[e];
        acc_h8(a, __ldg((const uint4*)(mA + ((size_t)s << 5) + woff)));
    }
    e = offB[g]; end = offB[g + 1];
    for (; e < end; e++) {
        int s = csrB[e];
        acc_h8(b, __ldg((const uint4*)(mB + ((size_t)s << 5) + woff)));
    }
    float da = dA[g], db = dB[g];
    int c0 = q << 3;
    float4 bAv0 = __ldg((const float4*)(bA + c0)), bAv1 = __ldg((const float4*)(bA + c0 + 4));
    float4 bBv0 = __ldg((const float4*)(bB + c0)), bBv1 = __ldg((const float4*)(bB + c0 + 4));
    float4 o0, o1;
    o0.x = fmaxf(0.5f * (da * a[0] + db * b[0] + bAv0.x + bBv0.x), 0.f);
    o0.y = fmaxf(0.5f * (da * a[1] + db * b[1] + bAv0.y + bBv0.y), 0.f);
    o0.z = fmaxf(0.5f * (da * a[2] + db * b[2] + bAv0.z + bBv0.z), 0.f);
    o0.w = fmaxf(0.5f * (da * a[3] + db * b[3] + bAv0.w + bBv0.w), 0.f);
    o1.x = fmaxf(0.5f * (da * a[4] + db * b[4] + bAv1.x + bBv1.x), 0.f);
    o1.y = fmaxf(0.5f * (da * a[5] + db * b[5] + bAv1.y + bBv1.y), 0.f);
    o1.z = fmaxf(0.5f * (da * a[6] + db * b[6] + bAv1.z + bBv1.z), 0.f);
    o1.w = fmaxf(0.5f * (da * a[7] + db * b[7] + bAv1.w + bBv1.w), 0.f);
    float4* op = (float4*)(Out + ((size_t)g << 6) + c0);
    op[0] = o0; op[1] = o1;
}

#define AU_B ((NUc * 8 + 255) / 256)
#define AT_B ((NTc * 8 + 255) / 256)

__global__ void __launch_bounds__(256) agg_kernel(const float* __restrict__ B) {
    int b = blockIdx.x;
    if (b < AU_B) {
        agg_body(b * 256 + threadIdx.x,
                 g_mu0h, g_off_u2u, g_csr_u2u, g_d_u2u,
                 g_mt1h, g_off_t2u, g_csr_t2u, g_dd_t2u,
                 B + 0 * 64, B + 3 * 64, g_hu, NUc);
    } else {
        agg_body((b - AU_B) * 256 + threadIdx.x,
                 g_mt0h, g_off_t2t, g_csr_t2t, g_d_t2t,
                 g_mu1h, g_off_u2t, g_csr_u2t, g_dd_u2t,
                 B + 1 * 64, B + 2 * 64, g_ht, NTc);
    }
}

// ---------------- readout ----------------
#define CS_BLOCKS 296
__global__ void colsum_kernel() {
    int b = blockIdx.x;
    if (b < CS_BLOCKS) {
        int t = b * blockDim.x + threadIdx.x;
        float s = 0.f;
        const int n = NUc * 64;
        for (int i = t; i < n; i += CS_BLOCKS * 256) s += g_hu[i];
        atomicAdd(&g_colsum[t & 63], s);
    } else {
        int t = (b - CS_BLOCKS) * blockDim.x + threadIdx.x;
        float s = 0.f;
        const int n = NTc * 64;
        for (int i = t; i < n; i += CS_BLOCKS * 256) s += g_ht[i];
        atomicAdd(&g_colsum[64 + (t & 63)], s);
    }
}

__global__ void mlp_kernel(const float* __restrict__ W1, const float* __restrict__ b1,
                           const float* __restrict__ W2, const float* __restrict__ b2,
                           float* __restrict__ out) {
    __shared__ float x[64];
    __shared__ float y[64];
    int t = threadIdx.x;
    x[t] = 0.5f * (g_colsum[t] * (1.f / NUc) + g_colsum[64 + t] * (1.f / NTc));
    __syncthreads();
    float s = b1[t];
    for (int k = 0; k < 64; k++) s += x[k] * W1[k * 64 + t];
    y[t] = fmaxf(s, 0.f) * W2[t];
    __syncthreads();
    if (t == 0) {
        float o = b2[0];
        for (int j = 0; j < 64; j++) o += y[j];
        out[0] = 1.f / (1.f + expf(-o));
    }
}

// ---------------- launch ----------------
extern "C" void kernel_launch(void* const* d_in, const int* in_sizes, int n_in,
                              void* d_out, int out_size) {
    const float* x_user     = (const float*)d_in[0];
    const float* x_txn      = (const float*)d_in[1];
    const int*   ei_u2u     = (const int*)d_in[2];
    const int*   ei_t2t     = (const int*)d_in[3];
    const int*   ei_u2t     = (const int*)d_in[4];
    const int*   ei_t2u     = (const int*)d_in[5];
    const float* W_emb_user = (const float*)d_in[6];
    const float* b_emb_user = (const float*)d_in[7];
    const float* W_emb_txn  = (const float*)d_in[8];
    const float* b_emb_txn  = (const float*)d_in[9];
    const float* conv_W     = (const float*)d_in[10];
    const float* conv_b     = (const float*)d_in[11];
    const float* W1         = (const float*)d_in[12];
    const float* b1         = (const float*)d_in[13];
    const float* W2         = (const float*)d_in[14];
    const float* b2         = (const float*)d_in[15];
    float* out = (float*)d_out;

    const int SMEM_DUAL = (2 * 4096 + 128 * 72) * 4;   // 69632
    const int SMEM_SNGL = (4096 + 128 * 72) * 4;       // 53248
    cudaFuncSetAttribute(transform_kernel, cudaFuncAttributeMaxDynamicSharedMemorySize, SMEM_DUAL);
    cudaFuncSetAttribute(embed_txn_kernel, cudaFuncAttributeMaxDynamicSharedMemorySize, SMEM_SNGL);

    // ---- CSR + norms (edge structure is layer-invariant) ----
    zero_cnt_kernel<<<(NTc + 255) / 256, 256>>>();
    count_kernel<<<(Ec + 255) / 256, 256>>>(ei_u2u, ei_t2t, ei_u2t, ei_t2u);
    scan4_kernel<<<4, 1024>>>();
    fill_kernel<<<(Ec + 255) / 256, 256>>>(ei_u2u, ei_t2t, ei_u2t, ei_t2u);
    dinv_kernel<<<(NTc + 255) / 256, 256>>>();

    // ---- embeddings ----
    embed_user_kernel<<<(NUc + 31) / 32, 256>>>(x_user, W_emb_user, b_emb_user);
    embed_txn_kernel<<<GT_T, 256, SMEM_SNGL>>>(x_txn, W_emb_txn, b_emb_txn);

    // ---- layers ----
    for (int l = 0; l < 3; l++) {
        const float* W = conv_W + (size_t)l * 4 * 64 * 64;
        const float* B = conv_b + (size_t)l * 4 * 64;
        transform_kernel<<<GU_T + GT_T, 256, SMEM_DUAL>>>(W);
        agg_kernel<<<AU_B + AT_B, 256>>>(B);
    }

    // ---- readout ----
    colsum_kernel<<<2 * CS_BLOCKS, 256>>>();
    mlp_kernel<<<1, 64>>>(W1, b1, W2, b2, out);
}